// round 14
// baseline (speedup 1.0000x reference)
#include <cuda_runtime.h>
#include <math.h>

#define NMAX 100000
#define EMAX 3200000

// ---------------- persistent device scratch (no runtime allocation) ----------------
// INVARIANT: g_deg and g_state are zero at every call exit (zero-initialized on the
// first call; re-zeroed inside agg_warp_k<1,true> each call). Deterministic per call.
__device__ int      g_csr_src[EMAX];   // src ids grouped by dst
__device__ int      g_deg[NMAX];       // in-degree
__device__ int      g_rowptr[NMAX];    // CSR row starts
__device__ int      g_cur[NMAX];       // scatter cursors
__device__ unsigned g_state[128];      // chained-scan published prefixes (flag|value)
__device__ float    g_h[NMAX * 32];    // transformed node features of current layer
__device__ float    g_S[NMAX * 32];    // aggregation numerator
__device__ float    g_as[NMAX * 2];    // per-node source attention coeff
__device__ float    g_ad[NMAX * 2];    // per-node dest attention coeff
__device__ float    g_den[NMAX * 2];   // softmax denominator (2-head layers)
__device__ float    g_den1[NMAX];      // softmax denominator (1-head layer)
__device__ int      g_is64;            // edge_index dtype flag

// ---- in-degree histogram straight from edge_index, 2 edges per thread ----
__global__ void hist_k(const void* __restrict__ ei, int E) {
    int t = blockIdx.x * blockDim.x + threadIdx.x;
    int e = t * 2;
    if (e >= E) return;
    if (g_is64) {
        const ulonglong2 p = *reinterpret_cast<const ulonglong2*>(
            (const long long*)ei + E + e);
        atomicAdd(&g_deg[(int)p.x], 1);
        atomicAdd(&g_deg[(int)p.y], 1);
    } else {
        const int2 p = *reinterpret_cast<const int2*>((const int*)ei + E + e);
        atomicAdd(&g_deg[p.x], 1);
        atomicAdd(&g_deg[p.y], 1);
    }
}

// ---------------- single-pass chained scan: degrees -> rowptr + cursors ----------
// Grid (<=98 blocks) fits in one wave on 148 SMs, so spinning on the previous
// block's published inclusive prefix cannot deadlock. g_state arrives zeroed.
__global__ void scan_k(int N) {
    __shared__ int wsum[32];
    __shared__ int s_excl;
    const int tid  = threadIdx.x;
    const int lane = tid & 31;
    const int wid  = tid >> 5;
    const int bid  = blockIdx.x;
    const int i = bid * 1024 + tid;
    const int v = (i < N) ? g_deg[i] : 0;

    // warp inclusive scan
    int s = v;
#pragma unroll
    for (int k = 1; k < 32; k <<= 1) {
        int t = __shfl_up_sync(0xffffffffu, s, k);
        if (lane >= k) s += t;
    }
    if (lane == 31) wsum[wid] = s;
    __syncthreads();
    if (wid == 0) {
        int w = wsum[lane];
#pragma unroll
        for (int k = 1; k < 32; k <<= 1) {
            int t = __shfl_up_sync(0xffffffffu, w, k);
            if (lane >= k) w += t;
        }
        wsum[lane] = w;
    }
    __syncthreads();
    const int add  = (wid > 0) ? wsum[wid - 1] : 0;
    const int incl = s + add;                // inclusive within block

    if (tid == 0) {
        int excl = 0;
        if (bid > 0) {
            unsigned st;
            do {
                st = atomicOr(&g_state[bid - 1], 0u);   // polling read
            } while (!(st & 0x80000000u));
            excl = (int)(st & 0x7fffffffu);
        }
        const int total = wsum[31];
        atomicExch(&g_state[bid], 0x80000000u | (unsigned)(excl + total));
        s_excl = excl;
    }
    __syncthreads();
    if (i < N) {
        const int r = incl - v + s_excl;
        g_rowptr[i] = r;
        g_cur[i] = r;
    }
}

// ---- scatter src ids into CSR order, 2 edges per thread ----
__global__ void scatter_k(const void* __restrict__ ei, int E) {
    int t = blockIdx.x * blockDim.x + threadIdx.x;
    int e = t * 2;
    if (e >= E) return;
    int s0, d0, s1, d1;
    if (g_is64) {
        const ulonglong2 ps = *reinterpret_cast<const ulonglong2*>(
            (const long long*)ei + e);
        const ulonglong2 pd = *reinterpret_cast<const ulonglong2*>(
            (const long long*)ei + E + e);
        s0 = (int)ps.x; s1 = (int)ps.y;
        d0 = (int)pd.x; d1 = (int)pd.y;
    } else {
        const int2 ps = *reinterpret_cast<const int2*>((const int*)ei + e);
        const int2 pd = *reinterpret_cast<const int2*>((const int*)ei + E + e);
        s0 = ps.x; s1 = ps.y;
        d0 = pd.x; d1 = pd.y;
    }
    g_csr_src[atomicAdd(&g_cur[d0], 1)] = s0;
    g_csr_src[atomicAdd(&g_cur[d1], 1)] = s1;
}

// ---------------- node kernel: epilogue of prev layer (opt) + transform + att dots
// MODE 0: input = x, ALSO runs the edge-index dtype probe (launch #1, pre-hist).
// MODE 1: after layer1 (scale/1.05/elu/clip). MODE 2: after layer2.
// OH = heads of the NEW layer being prepared.
template <int MODE, int OH>
__global__ void node_k(const float* __restrict__ xin,
                       const float* __restrict__ W,
                       const float* __restrict__ att_s,
                       const float* __restrict__ att_d,
                       const float* __restrict__ bias,
                       const float* __restrict__ ea,
                       const int* __restrict__ ei32,
                       int N) {
    __shared__ float sh[128 * 33];
    __shared__ float Wsh[1024];      // Wsh[i*32+o] = W[o][i]
    __shared__ float s_att[64];

    const int tid  = threadIdx.x;
    const int base = blockIdx.x * 128;
    const int count = min(128, N - base);

    if (MODE == 0 && blockIdx.x == 0 && tid == 0) {
        int acc = 0;
        for (int k = 0; k < 512; k++) acc |= ei32[2 * k + 1];
        g_is64 = (acc == 0) ? 1 : 0;
    }

    for (int idx = tid; idx < 1024; idx += 128) {
        int o = idx >> 5, i = idx & 31;
        Wsh[i * 32 + o] = W[idx];
    }
    if (tid < 32) { s_att[tid] = att_s[tid]; s_att[32 + tid] = att_d[tid]; }

    for (int idx = tid; idx < count * 32; idx += 128) {
        float v = (MODE == 0) ? xin[base * 32 + idx] : g_S[base * 32 + idx];
        sh[(idx >> 5) * 33 + (idx & 31)] = v;
    }
    __syncthreads();

    const int n = base + tid;
    if (n < N) {
        float* row = &sh[tid * 33];
        if (MODE != 0) {
            const float d0 = g_den[n * 2 + 0] + 1e-16f;
            const float d1 = g_den[n * 2 + 1] + 1e-16f;
            float sc = 1.f;
            if (MODE == 1) {
                float t = tanhf(ea[0]);
                sc = (t < 0.1f) ? 1.f : t;
                sc *= 1.05f;   // h + 0.05*detach(h) == 1.05*h
            }
#pragma unroll
            for (int i = 0; i < 32; i++) {
                float v = row[i] / (i < 16 ? d0 : d1) + bias[i];
                if (MODE == 1) v *= sc;
                v = (v > 0.f) ? v : expm1f(v);         // elu
                v = fminf(3.f, fmaxf(-3.f, v));        // clip
                row[i] = v;
            }
        }
        float acc[32];
#pragma unroll
        for (int o = 0; o < 32; o++) acc[o] = 0.f;
#pragma unroll
        for (int i = 0; i < 32; i++) {
            const float xv = row[i];
#pragma unroll
            for (int o = 0; o < 32; o++) acc[o] += xv * Wsh[i * 32 + o];
        }
        constexpr int CH = 32 / OH;
#pragma unroll
        for (int h = 0; h < OH; h++) {
            float as = 0.f, ad = 0.f;
#pragma unroll
            for (int c = 0; c < CH; c++) {
                as += acc[h * CH + c] * s_att[h * CH + c];
                ad += acc[h * CH + c] * s_att[32 + h * CH + c];
            }
            g_as[n * OH + h] = as;
            g_ad[n * OH + h] = ad;
        }
#pragma unroll
        for (int o = 0; o < 32; o++) row[o] = acc[o];
    }
    __syncthreads();
    for (int idx = tid; idx < count * 32; idx += 128)
        g_h[base * 32 + idx] = sh[(idx >> 5) * 33 + (idx & 31)];
}

// ---------------- SINGLE-PASS warp-per-node aggregation (champion hot loop) -------
// 4 edge-slots x 8 channel-lanes; flat per-lane loop, zero warp communication
// inside the loop. FINAL=true (layer 3): writes normalized output + bias straight
// to d_out and re-zeroes the per-call bookkeeping (g_deg, g_state).
template <int H, bool FINAL>
__global__ void agg_warp_k(int N, float slope,
                           const float* __restrict__ bias,
                           float* __restrict__ outp) {
    const int warp = (blockIdx.x * blockDim.x + threadIdx.x) >> 5;
    if (warp >= N) return;                 // uniform per warp
    const int lane  = threadIdx.x & 31;
    const int eslot = lane >> 3;           // 0..3
    const int j     = lane & 7;            // channel group (16B each)
    const int head  = (H == 2) ? (j >> 2) : 0;

    const int beg = g_rowptr[warp];
    const int deg = g_deg[warp];
    const float adh = g_ad[warp * H + head];

    if (FINAL && lane == 0) {
        g_deg[warp] = 0;                   // invariant: zero at call exit
        if (warp < 128) g_state[warp] = 0;
    }

    float4 acc = make_float4(0.f, 0.f, 0.f, 0.f);
    float den = 0.f;
#pragma unroll 4
    for (int i = eslot; i < deg; i += 4) {
        const int s = __ldg(&g_csr_src[beg + i]);
        float l = __ldg(&g_as[s * H + head]) + adh;
        l = (l > 0.f) ? l : l * slope;
        const float ex = __expf(l);
        const float4 hv = *reinterpret_cast<const float4*>(&g_h[(size_t)s * 32 + j * 4]);
        acc.x += ex * hv.x;
        acc.y += ex * hv.y;
        acc.z += ex * hv.z;
        acc.w += ex * hv.w;
        den += ex;
    }
    // combine eslots (lanes differing in bits 3,4 share j and head)
#pragma unroll
    for (int k = 8; k < 32; k <<= 1) {
        acc.x += __shfl_xor_sync(0xffffffffu, acc.x, k);
        acc.y += __shfl_xor_sync(0xffffffffu, acc.y, k);
        acc.z += __shfl_xor_sync(0xffffffffu, acc.z, k);
        acc.w += __shfl_xor_sync(0xffffffffu, acc.w, k);
        den   += __shfl_xor_sync(0xffffffffu, den, k);
    }

    if (eslot == 0) {
        if (FINAL) {
            const float inv = 1.f / (den + 1e-16f);
            const float4 bv = *reinterpret_cast<const float4*>(&bias[j * 4]);
            *reinterpret_cast<float4*>(&outp[(size_t)warp * 32 + j * 4]) =
                make_float4(acc.x * inv + bv.x, acc.y * inv + bv.y,
                            acc.z * inv + bv.z, acc.w * inv + bv.w);
        } else {
            *reinterpret_cast<float4*>(&g_S[(size_t)warp * 32 + j * 4]) = acc;
            if (H == 2) {
                if (j == 0) g_den[warp * 2 + 0] = den;
                if (j == 4) g_den[warp * 2 + 1] = den;
            } else {
                if (j == 0) g_den1[warp] = den;
            }
        }
    }
}

extern "C" void kernel_launch(void* const* d_in, const int* in_sizes, int n_in,
                              void* d_out, int out_size) {
    const float* x   = (const float*)d_in[0];
    const void*  ei  = d_in[1];
    const float* W1  = (const float*)d_in[2];
    const float* as1 = (const float*)d_in[3];
    const float* ad1 = (const float*)d_in[4];
    const float* b1  = (const float*)d_in[5];
    const float* ea1 = (const float*)d_in[6];
    const float* W2  = (const float*)d_in[7];
    const float* as2 = (const float*)d_in[8];
    const float* ad2 = (const float*)d_in[9];
    const float* b2  = (const float*)d_in[10];
    const float* W3  = (const float*)d_in[11];
    const float* as3 = (const float*)d_in[12];
    const float* ad3 = (const float*)d_in[13];
    const float* b3  = (const float*)d_in[14];
    float* out = (float*)d_out;

    const int N  = in_sizes[0] / 32;
    const int E  = in_sizes[1] / 2;
    const int nb = (N + 127) / 128;
    const int e2 = (E / 2 + 255) / 256;    // 2 edges per thread
    const int wb = (int)(((long long)N * 32 + 255) / 256);
    const int sb = (N + 1023) / 1024;

    // #1: layer-1 node transform (CSR-independent) + dtype probe
    node_k<0, 2><<<nb, 128>>>(x, W1, as1, ad1, nullptr, nullptr, (const int*)ei, N);
    // #2-#4: CSR build (g_deg/g_state arrive zeroed from previous call)
    hist_k<<<e2, 256>>>(ei, E);
    scan_k<<<sb, 1024>>>(N);
    scatter_k<<<e2, 256>>>(ei, E);
    // #5: layer-1 aggregation
    agg_warp_k<2, false><<<wb, 256>>>(N, 0.01f, nullptr, nullptr);

    // ---- layer 2 (slope 0.2, H=2) ----
    node_k<1, 2><<<nb, 128>>>(nullptr, W2, as2, ad2, b1, ea1, nullptr, N);
    agg_warp_k<2, false><<<wb, 256>>>(N, 0.2f, nullptr, nullptr);

    // ---- layer 3 (slope 0.2, H=1): aggregation fused with normalize+bias+output,
    //      also re-zeroes g_deg/g_state for the next call ----
    node_k<2, 1><<<nb, 128>>>(nullptr, W3, as3, ad3, b2, nullptr, nullptr, N);
    agg_warp_k<1, true><<<wb, 256>>>(N, 0.2f, b3, out);
}

// round 15
// speedup vs baseline: 1.0909x; 1.0909x over previous
#include <cuda_runtime.h>
#include <math.h>

#define NMAX 100000
#define EMAX 3200000

// ---------------- persistent device scratch (no runtime allocation) ----------------
// INVARIANT: g_deg is zero at every call exit (zero-initialized on the first call;
// re-zeroed inside agg_warp_k<1,true> each call). Deterministic per call.
__device__ int   g_csr_src[EMAX];    // src ids grouped by dst
__device__ int   g_deg[NMAX];        // in-degree
__device__ int   g_rowptr[NMAX];     // CSR row starts
__device__ int   g_cur[NMAX];        // scatter cursors
__device__ int   g_bsum[128];        // scan block sums
__device__ float g_h[NMAX * 32];     // transformed node features of current layer
__device__ float g_S[NMAX * 32];     // aggregation numerator
__device__ float g_as[NMAX * 2];     // per-node source attention coeff
__device__ float g_ad[NMAX * 2];     // per-node dest attention coeff
__device__ float g_den[NMAX * 2];    // softmax denominator (2-head layers)
__device__ float g_den1[NMAX];       // softmax denominator (1-head layer)
__device__ int   g_is64;             // edge_index dtype flag

// ---- in-degree histogram straight from edge_index, 2 edges per thread ----
__global__ void hist_k(const void* __restrict__ ei, int E) {
    int t = blockIdx.x * blockDim.x + threadIdx.x;
    int e = t * 2;
    if (e >= E) return;
    if (g_is64) {
        const ulonglong2 p = *reinterpret_cast<const ulonglong2*>(
            (const long long*)ei + E + e);
        atomicAdd(&g_deg[(int)p.x], 1);
        atomicAdd(&g_deg[(int)p.y], 1);
    } else {
        const int2 p = *reinterpret_cast<const int2*>((const int*)ei + E + e);
        atomicAdd(&g_deg[p.x], 1);
        atomicAdd(&g_deg[p.y], 1);
    }
}

// ---------------- scan over degrees -> rowptr (warp-shuffle based, 2 kernels) -----
__global__ void scanA_k(int N) {
    __shared__ int wsum[32];
    const int tid  = threadIdx.x;
    const int lane = tid & 31;
    const int wid  = tid >> 5;
    const int i = blockIdx.x * 1024 + tid;
    const int v = (i < N) ? g_deg[i] : 0;

    int s = v;
#pragma unroll
    for (int k = 1; k < 32; k <<= 1) {
        int t = __shfl_up_sync(0xffffffffu, s, k);
        if (lane >= k) s += t;
    }
    if (lane == 31) wsum[wid] = s;
    __syncthreads();
    if (wid == 0) {
        int w = wsum[lane];
#pragma unroll
        for (int k = 1; k < 32; k <<= 1) {
            int t = __shfl_up_sync(0xffffffffu, w, k);
            if (lane >= k) w += t;
        }
        wsum[lane] = w;
    }
    __syncthreads();
    const int add = (wid > 0) ? wsum[wid - 1] : 0;
    if (i < N) g_rowptr[i] = s + add - v;           // exclusive within block
    if (tid == 1023) g_bsum[blockIdx.x] = s + add;  // block total
}

// apply block offsets; block-sum scan done redundantly per block by warp 0
__global__ void scanC_k(int N, int nb) {
    __shared__ int so[128];
    const int tid = threadIdx.x;
    if (tid < 32) {
        int a0 = (tid < nb)      ? g_bsum[tid]      : 0;
        int a1 = (tid + 32 < nb) ? g_bsum[tid + 32] : 0;
        int a2 = (tid + 64 < nb) ? g_bsum[tid + 64] : 0;
        int a3 = (tid + 96 < nb) ? g_bsum[tid + 96] : 0;
        int s0 = a0, s1 = a1, s2 = a2, s3 = a3;
#pragma unroll
        for (int k = 1; k < 32; k <<= 1) {
            int t0 = __shfl_up_sync(0xffffffffu, s0, k);
            int t1 = __shfl_up_sync(0xffffffffu, s1, k);
            int t2 = __shfl_up_sync(0xffffffffu, s2, k);
            int t3 = __shfl_up_sync(0xffffffffu, s3, k);
            if (tid >= k) { s0 += t0; s1 += t1; s2 += t2; s3 += t3; }
        }
        const int tot0 = __shfl_sync(0xffffffffu, s0, 31);
        const int tot1 = __shfl_sync(0xffffffffu, s1, 31);
        const int tot2 = __shfl_sync(0xffffffffu, s2, 31);
        so[tid]      = s0;
        so[tid + 32] = s1 + tot0;
        so[tid + 64] = s2 + tot0 + tot1;
        so[tid + 96] = s3 + tot0 + tot1 + tot2;
    }
    __syncthreads();
    int i = blockIdx.x * blockDim.x + tid;
    if (i < N) {
        const int blk = i >> 10;
        const int off = (blk == 0) ? 0 : so[blk - 1];
        const int r = g_rowptr[i] + off;
        g_rowptr[i] = r;
        g_cur[i] = r;
    }
}

// ---- scatter src ids into CSR order, 4 independent edge-chains per thread ----
__global__ void scatter_k(const void* __restrict__ ei, int E) {
    int t = blockIdx.x * blockDim.x + threadIdx.x;
    int e = t * 4;
    if (e >= E) return;
    int s[4], d[4];
    const int m = min(4, E - e);
    if (g_is64) {
        const long long* ps = (const long long*)ei + e;
        const long long* pd = (const long long*)ei + E + e;
#pragma unroll
        for (int q = 0; q < 4; q++) {
            if (q < m) { s[q] = (int)ps[q]; d[q] = (int)pd[q]; }
        }
    } else {
        const int* ps = (const int*)ei + e;
        const int* pd = (const int*)ei + E + e;
#pragma unroll
        for (int q = 0; q < 4; q++) {
            if (q < m) { s[q] = ps[q]; d[q] = pd[q]; }
        }
    }
    int pos[4];
#pragma unroll
    for (int q = 0; q < 4; q++)
        if (q < m) pos[q] = atomicAdd(&g_cur[d[q]], 1);   // 4 independent RMWs
#pragma unroll
    for (int q = 0; q < 4; q++)
        if (q < m) g_csr_src[pos[q]] = s[q];
}

// ---------------- node kernel: epilogue of prev layer (opt) + transform + att dots
// MODE 0: input = x, ALSO runs the edge-index dtype probe (launch #1, pre-hist).
// MODE 1: after layer1 (scale/1.05/elu/clip). MODE 2: after layer2.
// OH = heads of the NEW layer being prepared.
template <int MODE, int OH>
__global__ void node_k(const float* __restrict__ xin,
                       const float* __restrict__ W,
                       const float* __restrict__ att_s,
                       const float* __restrict__ att_d,
                       const float* __restrict__ bias,
                       const float* __restrict__ ea,
                       const int* __restrict__ ei32,
                       int N) {
    __shared__ float sh[128 * 33];
    __shared__ float Wsh[1024];      // Wsh[i*32+o] = W[o][i]
    __shared__ float s_att[64];

    const int tid  = threadIdx.x;
    const int base = blockIdx.x * 128;
    const int count = min(128, N - base);

    if (MODE == 0 && blockIdx.x == 0 && tid == 0) {
        int acc = 0;
        for (int k = 0; k < 512; k++) acc |= ei32[2 * k + 1];
        g_is64 = (acc == 0) ? 1 : 0;
    }

    for (int idx = tid; idx < 1024; idx += 128) {
        int o = idx >> 5, i = idx & 31;
        Wsh[i * 32 + o] = W[idx];
    }
    if (tid < 32) { s_att[tid] = att_s[tid]; s_att[32 + tid] = att_d[tid]; }

    for (int idx = tid; idx < count * 32; idx += 128) {
        float v = (MODE == 0) ? xin[base * 32 + idx] : g_S[base * 32 + idx];
        sh[(idx >> 5) * 33 + (idx & 31)] = v;
    }
    __syncthreads();

    const int n = base + tid;
    if (n < N) {
        float* row = &sh[tid * 33];
        if (MODE != 0) {
            const float d0 = g_den[n * 2 + 0] + 1e-16f;
            const float d1 = g_den[n * 2 + 1] + 1e-16f;
            float sc = 1.f;
            if (MODE == 1) {
                float t = tanhf(ea[0]);
                sc = (t < 0.1f) ? 1.f : t;
                sc *= 1.05f;   // h + 0.05*detach(h) == 1.05*h
            }
#pragma unroll
            for (int i = 0; i < 32; i++) {
                float v = row[i] / (i < 16 ? d0 : d1) + bias[i];
                if (MODE == 1) v *= sc;
                v = (v > 0.f) ? v : expm1f(v);         // elu
                v = fminf(3.f, fmaxf(-3.f, v));        // clip
                row[i] = v;
            }
        }
        float acc[32];
#pragma unroll
        for (int o = 0; o < 32; o++) acc[o] = 0.f;
#pragma unroll
        for (int i = 0; i < 32; i++) {
            const float xv = row[i];
#pragma unroll
            for (int o = 0; o < 32; o++) acc[o] += xv * Wsh[i * 32 + o];
        }
        constexpr int CH = 32 / OH;
#pragma unroll
        for (int h = 0; h < OH; h++) {
            float as = 0.f, ad = 0.f;
#pragma unroll
            for (int c = 0; c < CH; c++) {
                as += acc[h * CH + c] * s_att[h * CH + c];
                ad += acc[h * CH + c] * s_att[32 + h * CH + c];
            }
            g_as[n * OH + h] = as;
            g_ad[n * OH + h] = ad;
        }
#pragma unroll
        for (int o = 0; o < 32; o++) row[o] = acc[o];
    }
    __syncthreads();
    for (int idx = tid; idx < count * 32; idx += 128)
        g_h[base * 32 + idx] = sh[(idx >> 5) * 33 + (idx & 31)];
}

// ---------------- SINGLE-PASS warp-per-node aggregation (champion hot loop) -------
// 4 edge-slots x 8 channel-lanes; flat per-lane loop, zero warp communication
// inside the loop. FINAL=true (layer 3): writes normalized output + bias straight
// to d_out and re-zeroes g_deg (per-call invariant).
template <int H, bool FINAL>
__global__ void agg_warp_k(int N, float slope,
                           const float* __restrict__ bias,
                           float* __restrict__ outp) {
    const int warp = (blockIdx.x * blockDim.x + threadIdx.x) >> 5;
    if (warp >= N) return;                 // uniform per warp
    const int lane  = threadIdx.x & 31;
    const int eslot = lane >> 3;           // 0..3
    const int j     = lane & 7;            // channel group (16B each)
    const int head  = (H == 2) ? (j >> 2) : 0;

    const int beg = g_rowptr[warp];
    const int deg = g_deg[warp];
    const float adh = g_ad[warp * H + head];

    if (FINAL && lane == 0) g_deg[warp] = 0;   // invariant: zero at call exit

    float4 acc = make_float4(0.f, 0.f, 0.f, 0.f);
    float den = 0.f;
#pragma unroll 4
    for (int i = eslot; i < deg; i += 4) {
        const int s = __ldg(&g_csr_src[beg + i]);
        float l = __ldg(&g_as[s * H + head]) + adh;
        l = (l > 0.f) ? l : l * slope;
        const float ex = __expf(l);
        const float4 hv = *reinterpret_cast<const float4*>(&g_h[(size_t)s * 32 + j * 4]);
        acc.x += ex * hv.x;
        acc.y += ex * hv.y;
        acc.z += ex * hv.z;
        acc.w += ex * hv.w;
        den += ex;
    }
    // combine eslots (lanes differing in bits 3,4 share j and head)
#pragma unroll
    for (int k = 8; k < 32; k <<= 1) {
        acc.x += __shfl_xor_sync(0xffffffffu, acc.x, k);
        acc.y += __shfl_xor_sync(0xffffffffu, acc.y, k);
        acc.z += __shfl_xor_sync(0xffffffffu, acc.z, k);
        acc.w += __shfl_xor_sync(0xffffffffu, acc.w, k);
        den   += __shfl_xor_sync(0xffffffffu, den, k);
    }

    if (eslot == 0) {
        if (FINAL) {
            const float inv = 1.f / (den + 1e-16f);
            const float4 bv = *reinterpret_cast<const float4*>(&bias[j * 4]);
            *reinterpret_cast<float4*>(&outp[(size_t)warp * 32 + j * 4]) =
                make_float4(acc.x * inv + bv.x, acc.y * inv + bv.y,
                            acc.z * inv + bv.z, acc.w * inv + bv.w);
        } else {
            *reinterpret_cast<float4*>(&g_S[(size_t)warp * 32 + j * 4]) = acc;
            if (H == 2) {
                if (j == 0) g_den[warp * 2 + 0] = den;
                if (j == 4) g_den[warp * 2 + 1] = den;
            } else {
                if (j == 0) g_den1[warp] = den;
            }
        }
    }
}

extern "C" void kernel_launch(void* const* d_in, const int* in_sizes, int n_in,
                              void* d_out, int out_size) {
    const float* x   = (const float*)d_in[0];
    const void*  ei  = d_in[1];
    const float* W1  = (const float*)d_in[2];
    const float* as1 = (const float*)d_in[3];
    const float* ad1 = (const float*)d_in[4];
    const float* b1  = (const float*)d_in[5];
    const float* ea1 = (const float*)d_in[6];
    const float* W2  = (const float*)d_in[7];
    const float* as2 = (const float*)d_in[8];
    const float* ad2 = (const float*)d_in[9];
    const float* b2  = (const float*)d_in[10];
    const float* W3  = (const float*)d_in[11];
    const float* as3 = (const float*)d_in[12];
    const float* ad3 = (const float*)d_in[13];
    const float* b3  = (const float*)d_in[14];
    float* out = (float*)d_out;

    const int N  = in_sizes[0] / 32;
    const int E  = in_sizes[1] / 2;
    const int nb = (N + 127) / 128;
    const int e2 = (E / 2 + 255) / 256;    // 2 edges per thread (hist)
    const int e4 = (E / 4 + 255) / 256;    // 4 edges per thread (scatter)
    const int wb = (int)(((long long)N * 32 + 255) / 256);
    const int sb = (N + 1023) / 1024;

    // #1: layer-1 node transform (CSR-independent) + dtype probe
    node_k<0, 2><<<nb, 128>>>(x, W1, as1, ad1, nullptr, nullptr, (const int*)ei, N);
    // #2-#5: CSR build (g_deg arrives zeroed from previous call / initial state)
    hist_k<<<e2, 256>>>(ei, E);
    scanA_k<<<sb, 1024>>>(N);
    scanC_k<<<(N + 255) / 256, 256>>>(N, sb);
    scatter_k<<<e4, 256>>>(ei, E);
    // #6: layer-1 aggregation
    agg_warp_k<2, false><<<wb, 256>>>(N, 0.01f, nullptr, nullptr);

    // ---- layer 2 (slope 0.2, H=2) ----
    node_k<1, 2><<<nb, 128>>>(nullptr, W2, as2, ad2, b1, ea1, nullptr, N);
    agg_warp_k<2, false><<<wb, 256>>>(N, 0.2f, nullptr, nullptr);

    // ---- layer 3 (slope 0.2, H=1): aggregation fused with normalize+bias+output,
    //      also re-zeroes g_deg for the next call ----
    node_k<2, 1><<<nb, 128>>>(nullptr, W3, as3, ad3, b2, nullptr, nullptr, N);
    agg_warp_k<1, true><<<wb, 256>>>(N, 0.2f, b3, out);
}

// round 16
// speedup vs baseline: 1.5079x; 1.3822x over previous
#include <cuda_runtime.h>
#include <math.h>

#define NMAX 100000
#define EMAX 3200000

// ---------------- persistent device scratch (no runtime allocation) ----------------
// NOTE: g_deg relies on zero-initialized __device__ state on the FIRST call and is
// re-zeroed by final_k at the end of EVERY call (deterministic, same work each call).
__device__ int   g_csr_src[EMAX];    // src ids grouped by dst
__device__ int   g_deg[NMAX];        // in-degree (zeroed at end of each call)
__device__ int   g_rowptr[NMAX];     // CSR row starts
__device__ int   g_cur[NMAX];        // scatter cursors
__device__ int   g_bsum[128];        // scan block sums
__device__ float g_h[NMAX * 32];     // transformed node features of current layer
__device__ float g_S[NMAX * 32];     // aggregation numerator
__device__ float g_as[NMAX * 2];     // per-node source attention coeff
__device__ float g_ad[NMAX * 2];     // per-node dest attention coeff
__device__ float g_den[NMAX * 2];    // softmax denominator (2-head layers)
__device__ float g_den1[NMAX];       // softmax denominator (1-head layer)
__device__ int   g_is64;             // edge_index dtype flag

// ---- in-degree histogram straight from edge_index, 2 edges per thread ----
__global__ void hist_k(const void* __restrict__ ei, int E) {
    int t = blockIdx.x * blockDim.x + threadIdx.x;
    int e = t * 2;
    if (e >= E) return;
    if (g_is64) {
        const ulonglong2 p = *reinterpret_cast<const ulonglong2*>(
            (const long long*)ei + E + e);
        atomicAdd(&g_deg[(int)p.x], 1);
        atomicAdd(&g_deg[(int)p.y], 1);
    } else {
        const int2 p = *reinterpret_cast<const int2*>((const int*)ei + E + e);
        atomicAdd(&g_deg[p.x], 1);
        atomicAdd(&g_deg[p.y], 1);
    }
}

// ---------------- scan over degrees -> rowptr (warp-shuffle based) ----------------
__global__ void scanA_k(int N) {
    __shared__ int wsum[32];
    const int tid  = threadIdx.x;
    const int lane = tid & 31;
    const int wid  = tid >> 5;
    const int i = blockIdx.x * 1024 + tid;
    const int v = (i < N) ? g_deg[i] : 0;

    // warp inclusive scan
    int s = v;
#pragma unroll
    for (int k = 1; k < 32; k <<= 1) {
        int t = __shfl_up_sync(0xffffffffu, s, k);
        if (lane >= k) s += t;
    }
    if (lane == 31) wsum[wid] = s;
    __syncthreads();
    if (wid == 0) {
        int w = wsum[lane];
#pragma unroll
        for (int k = 1; k < 32; k <<= 1) {
            int t = __shfl_up_sync(0xffffffffu, w, k);
            if (lane >= k) w += t;
        }
        wsum[lane] = w;
    }
    __syncthreads();
    const int add = (wid > 0) ? wsum[wid - 1] : 0;
    if (i < N) g_rowptr[i] = s + add - v;           // exclusive within block
    if (tid == 1023) g_bsum[blockIdx.x] = s + add;  // block total
}

// apply block offsets; block-sum scan done redundantly per block by warp 0
__global__ void scanC_k(int N, int nb) {
    __shared__ int so[128];
    const int tid = threadIdx.x;
    if (tid < 32) {
        // scan 128 block sums with one warp: 4 values per lane, sequential-of-shfl
        int a0 = (tid < nb)       ? g_bsum[tid]       : 0;
        int a1 = (tid + 32 < nb)  ? g_bsum[tid + 32]  : 0;
        int a2 = (tid + 64 < nb)  ? g_bsum[tid + 64]  : 0;
        int a3 = (tid + 96 < nb)  ? g_bsum[tid + 96]  : 0;
        // inclusive scan of each 32-chunk
        int s0 = a0, s1 = a1, s2 = a2, s3 = a3;
#pragma unroll
        for (int k = 1; k < 32; k <<= 1) {
            int t0 = __shfl_up_sync(0xffffffffu, s0, k);
            int t1 = __shfl_up_sync(0xffffffffu, s1, k);
            int t2 = __shfl_up_sync(0xffffffffu, s2, k);
            int t3 = __shfl_up_sync(0xffffffffu, s3, k);
            if (tid >= k) { s0 += t0; s1 += t1; s2 += t2; s3 += t3; }
        }
        const int tot0 = __shfl_sync(0xffffffffu, s0, 31);
        const int tot1 = __shfl_sync(0xffffffffu, s1, 31);
        const int tot2 = __shfl_sync(0xffffffffu, s2, 31);
        so[tid]      = s0;
        so[tid + 32] = s1 + tot0;
        so[tid + 64] = s2 + tot0 + tot1;
        so[tid + 96] = s3 + tot0 + tot1 + tot2;
    }
    __syncthreads();
    int i = blockIdx.x * blockDim.x + tid;
    if (i < N) {
        const int blk = i >> 10;
        const int off = (blk == 0) ? 0 : so[blk - 1];
        const int r = g_rowptr[i] + off;
        g_rowptr[i] = r;
        g_cur[i] = r;
    }
}

// ---- scatter src ids into CSR order, 2 edges per thread ----
__global__ void scatter_k(const void* __restrict__ ei, int E) {
    int t = blockIdx.x * blockDim.x + threadIdx.x;
    int e = t * 2;
    if (e >= E) return;
    int s0, d0, s1, d1;
    if (g_is64) {
        const ulonglong2 ps = *reinterpret_cast<const ulonglong2*>(
            (const long long*)ei + e);
        const ulonglong2 pd = *reinterpret_cast<const ulonglong2*>(
            (const long long*)ei + E + e);
        s0 = (int)ps.x; s1 = (int)ps.y;
        d0 = (int)pd.x; d1 = (int)pd.y;
    } else {
        const int2 ps = *reinterpret_cast<const int2*>((const int*)ei + e);
        const int2 pd = *reinterpret_cast<const int2*>((const int*)ei + E + e);
        s0 = ps.x; s1 = ps.y;
        d0 = pd.x; d1 = pd.y;
    }
    g_csr_src[atomicAdd(&g_cur[d0], 1)] = s0;
    g_csr_src[atomicAdd(&g_cur[d1], 1)] = s1;
}

// ---------------- node kernel: epilogue of prev layer (opt) + transform + att dots
// MODE 0: input = x, ALSO runs the edge-index dtype probe (launch #1, pre-hist).
// MODE 1: after layer1 (scale/1.05/elu/clip). MODE 2: after layer2.
// OH = heads of the NEW layer being prepared.
template <int MODE, int OH>
__global__ void node_k(const float* __restrict__ xin,
                       const float* __restrict__ W,
                       const float* __restrict__ att_s,
                       const float* __restrict__ att_d,
                       const float* __restrict__ bias,
                       const float* __restrict__ ea,
                       const int* __restrict__ ei32,
                       int N) {
    __shared__ float sh[128 * 33];
    __shared__ float Wsh[1024];      // Wsh[i*32+o] = W[o][i]
    __shared__ float s_att[64];

    const int tid  = threadIdx.x;
    const int base = blockIdx.x * 128;
    const int count = min(128, N - base);

    if (MODE == 0 && blockIdx.x == 0 && tid == 0) {
        int acc = 0;
        for (int k = 0; k < 512; k++) acc |= ei32[2 * k + 1];
        g_is64 = (acc == 0) ? 1 : 0;
    }

    for (int idx = tid; idx < 1024; idx += 128) {
        int o = idx >> 5, i = idx & 31;
        Wsh[i * 32 + o] = W[idx];
    }
    if (tid < 32) { s_att[tid] = att_s[tid]; s_att[32 + tid] = att_d[tid]; }

    for (int idx = tid; idx < count * 32; idx += 128) {
        float v = (MODE == 0) ? xin[base * 32 + idx] : g_S[base * 32 + idx];
        sh[(idx >> 5) * 33 + (idx & 31)] = v;
    }
    __syncthreads();

    const int n = base + tid;
    if (n < N) {
        float* row = &sh[tid * 33];
        if (MODE != 0) {
            const float d0 = g_den[n * 2 + 0] + 1e-16f;
            const float d1 = g_den[n * 2 + 1] + 1e-16f;
            float sc = 1.f;
            if (MODE == 1) {
                float t = tanhf(ea[0]);
                sc = (t < 0.1f) ? 1.f : t;
                sc *= 1.05f;   // h + 0.05*detach(h) == 1.05*h
            }
#pragma unroll
            for (int i = 0; i < 32; i++) {
                float v = row[i] / (i < 16 ? d0 : d1) + bias[i];
                if (MODE == 1) v *= sc;
                v = (v > 0.f) ? v : expm1f(v);         // elu
                v = fminf(3.f, fmaxf(-3.f, v));        // clip
                row[i] = v;
            }
        }
        float acc[32];
#pragma unroll
        for (int o = 0; o < 32; o++) acc[o] = 0.f;
#pragma unroll
        for (int i = 0; i < 32; i++) {
            const float xv = row[i];
#pragma unroll
            for (int o = 0; o < 32; o++) acc[o] += xv * Wsh[i * 32 + o];
        }
        constexpr int CH = 32 / OH;
#pragma unroll
        for (int h = 0; h < OH; h++) {
            float as = 0.f, ad = 0.f;
#pragma unroll
            for (int c = 0; c < CH; c++) {
                as += acc[h * CH + c] * s_att[h * CH + c];
                ad += acc[h * CH + c] * s_att[32 + h * CH + c];
            }
            g_as[n * OH + h] = as;
            g_ad[n * OH + h] = ad;
        }
#pragma unroll
        for (int o = 0; o < 32; o++) row[o] = acc[o];
    }
    __syncthreads();
    for (int idx = tid; idx < count * 32; idx += 128)
        g_h[base * 32 + idx] = sh[(idx >> 5) * 33 + (idx & 31)];
}

// ---------------- SINGLE-PASS warp-per-node aggregation (champion form, UNCHANGED) -
// 4 edge-slots x 8 channel-lanes; flat per-lane loop, zero warp communication
// inside the loop. Per edge: as gather, exp, 16B h gather, FMA. shfl-ADD combine.
template <int H>
__global__ void agg_warp_k(int N, float slope) {
    const int warp = (blockIdx.x * blockDim.x + threadIdx.x) >> 5;
    if (warp >= N) return;                 // uniform per warp
    const int lane  = threadIdx.x & 31;
    const int eslot = lane >> 3;           // 0..3
    const int j     = lane & 7;            // channel group (16B each)
    const int head  = (H == 2) ? (j >> 2) : 0;

    const int beg = g_rowptr[warp];
    const int deg = g_deg[warp];
    const float adh = g_ad[warp * H + head];

    float4 acc = make_float4(0.f, 0.f, 0.f, 0.f);
    float den = 0.f;
#pragma unroll 4
    for (int i = eslot; i < deg; i += 4) {
        const int s = __ldg(&g_csr_src[beg + i]);
        float l = __ldg(&g_as[s * H + head]) + adh;
        l = (l > 0.f) ? l : l * slope;
        const float ex = __expf(l);
        const float4 hv = *reinterpret_cast<const float4*>(&g_h[(size_t)s * 32 + j * 4]);
        acc.x += ex * hv.x;
        acc.y += ex * hv.y;
        acc.z += ex * hv.z;
        acc.w += ex * hv.w;
        den += ex;
    }
    // combine eslots (lanes differing in bits 3,4 share j and head)
#pragma unroll
    for (int k = 8; k < 32; k <<= 1) {
        acc.x += __shfl_xor_sync(0xffffffffu, acc.x, k);
        acc.y += __shfl_xor_sync(0xffffffffu, acc.y, k);
        acc.z += __shfl_xor_sync(0xffffffffu, acc.z, k);
        acc.w += __shfl_xor_sync(0xffffffffu, acc.w, k);
        den   += __shfl_xor_sync(0xffffffffu, den, k);
    }

    if (eslot == 0) {
        *reinterpret_cast<float4*>(&g_S[(size_t)warp * 32 + j * 4]) = acc;
        if (H == 2) {
            if (j == 0) g_den[warp * 2 + 0] = den;
            if (j == 4) g_den[warp * 2 + 1] = den;
        } else {
            if (j == 0) g_den1[warp] = den;
        }
    }
}

// ---------------- final epilogue: normalize + bias; also re-zero g_deg ------------
__global__ void final_k(const float* __restrict__ b3, float* __restrict__ out, int N) {
    int idx = blockIdx.x * blockDim.x + threadIdx.x;
    if (idx < N * 32)
        out[idx] = g_S[idx] / (g_den1[idx >> 5] + 1e-16f) + b3[idx & 31];
    if (idx < N) g_deg[idx] = 0;   // invariant: g_deg zero at call exit
}

extern "C" void kernel_launch(void* const* d_in, const int* in_sizes, int n_in,
                              void* d_out, int out_size) {
    const float* x   = (const float*)d_in[0];
    const void*  ei  = d_in[1];
    const float* W1  = (const float*)d_in[2];
    const float* as1 = (const float*)d_in[3];
    const float* ad1 = (const float*)d_in[4];
    const float* b1  = (const float*)d_in[5];
    const float* ea1 = (const float*)d_in[6];
    const float* W2  = (const float*)d_in[7];
    const float* as2 = (const float*)d_in[8];
    const float* ad2 = (const float*)d_in[9];
    const float* b2  = (const float*)d_in[10];
    const float* W3  = (const float*)d_in[11];
    const float* as3 = (const float*)d_in[12];
    const float* ad3 = (const float*)d_in[13];
    const float* b3  = (const float*)d_in[14];
    float* out = (float*)d_out;

    const int N  = in_sizes[0] / 32;
    const int E  = in_sizes[1] / 2;
    const int nb = (N + 127) / 128;
    const int e2 = (E / 2 + 255) / 256;    // 2 edges per thread
    const int wb = (int)(((long long)N * 32 + 255) / 256);
    const int sb = (N + 1023) / 1024;

    // #1: layer-1 node transform (CSR-independent) + dtype probe
    node_k<0, 2><<<nb, 128>>>(x, W1, as1, ad1, nullptr, nullptr, (const int*)ei, N);
    // #2-#5: CSR build (g_deg arrives zeroed from previous call / initial state)
    hist_k<<<e2, 256>>>(ei, E);
    scanA_k<<<sb, 1024>>>(N);
    scanC_k<<<(N + 255) / 256, 256>>>(N, sb);
    scatter_k<<<e2, 256>>>(ei, E);
    // #6: layer-1 aggregation
    agg_warp_k<2><<<wb, 256>>>(N, 0.01f);

    // ---- layer 2 (slope 0.2, H=2) ----
    node_k<1, 2><<<nb, 128>>>(nullptr, W2, as2, ad2, b1, ea1, nullptr, N);
    agg_warp_k<2><<<wb, 256>>>(N, 0.2f);

    // ---- layer 3 (slope 0.2, H=1) ----
    node_k<2, 1><<<nb, 128>>>(nullptr, W3, as3, ad3, b2, nullptr, nullptr, N);
    agg_warp_k<1><<<wb, 256>>>(N, 0.2f);

    // epilogue + re-zero g_deg for the next call
    final_k<<<(N * 32 + 255) / 256, 256>>>(b3, out, N);
}